// round 1
// baseline (speedup 1.0000x reference)
#include <cuda_runtime.h>
#include <math.h>

// ---------------- problem constants ----------------
#define B_      32
#define DM      4096
#define H_      32
#define KV_     8
#define G_      4
#define HD_     128
#define BLOCK_  64
#define NBLK_   64
#define L_      4096
#define QKVC    6144   // (H + 2*KV) * HD
#define SPLITS  8      // split-K for GEMMs
#define SEGS    64     // attention segments per sequence (one 64-row block each)

// ---------------- scratch (__device__ globals; no allocation) ----------------
__device__ float g_qkv_part[SPLITS * B_ * QKVC];          // 6.3 MB
__device__ float g_q[B_ * H_ * HD_];                      // rope'd + pre-scaled q
__device__ float g_knew[B_ * KV_ * HD_];
__device__ float g_vnew[B_ * KV_ * HD_];
__device__ float g_attn_acc[(size_t)B_ * H_ * SEGS * HD_]; // 33.6 MB
__device__ float g_attn_ml[B_ * H_ * SEGS * 2];
__device__ float g_attn_out[B_ * DM];
__device__ float g_out_part[SPLITS * B_ * DM];            // 4 MB

// ---------------- split-K GEMM: out_part[s][b][col] = sum_{d in chunk} A[b][d]*W[d][col]
// A is [32][4096]; W is [4096][ncols]; which==0 -> (A_in, g_qkv_part), which==1 -> (g_attn_out, g_out_part)
__global__ __launch_bounds__(256) void gemm_splitk_kernel(
    const float* __restrict__ A_in, const float* __restrict__ W, int ncols, int which)
{
    __shared__ float hs[32][128];
    const float* A = which ? g_attn_out : A_in;
    float* part = which ? g_out_part : g_qkv_part;

    const int tid = threadIdx.x;
    const int tc = tid & 31;            // 32 col-groups of 4 cols
    const int tr = tid >> 5;            // 8 batch-groups of 4 batches
    const int col4 = blockIdx.x * 128 + tc * 4;
    const int s = blockIdx.y;

    float acc[4][4];
#pragma unroll
    for (int j = 0; j < 4; j++)
        acc[j][0] = acc[j][1] = acc[j][2] = acc[j][3] = 0.f;

    for (int sub = 0; sub < 4; sub++) {
        const int dd0 = s * 512 + sub * 128;
        // stage A[0:32][dd0:dd0+128]
        for (int i = tid; i < 1024; i += 256) {
            int bb = i >> 5;
            int cc = i & 31;
            *(float4*)&hs[bb][cc * 4] = *(const float4*)&A[bb * DM + dd0 + cc * 4];
        }
        __syncthreads();
#pragma unroll 4
        for (int dd = 0; dd < 128; dd++) {
            float4 w = *(const float4*)&W[(size_t)(dd0 + dd) * ncols + col4];
#pragma unroll
            for (int j = 0; j < 4; j++) {
                float h = hs[tr * 4 + j][dd];
                acc[j][0] = fmaf(h, w.x, acc[j][0]);
                acc[j][1] = fmaf(h, w.y, acc[j][1]);
                acc[j][2] = fmaf(h, w.z, acc[j][2]);
                acc[j][3] = fmaf(h, w.w, acc[j][3]);
            }
        }
        __syncthreads();
    }
#pragma unroll
    for (int j = 0; j < 4; j++) {
        int b = tr * 4 + j;
        *(float4*)&part[((size_t)s * 32 + b) * ncols + col4] =
            make_float4(acc[j][0], acc[j][1], acc[j][2], acc[j][3]);
    }
}

// ---------------- reduce qkv partials + RoPE + stash new k/v (no cache mutation)
__global__ __launch_bounds__(64) void rope_kernel(const int* __restrict__ pos_ids)
{
    const int h = blockIdx.x;   // 0..47: 0-31 q heads, 32-39 k heads, 40-47 v heads
    const int b = blockIdx.y;
    const int t = threadIdx.x;  // 0..63 (pair t, t+64)

    int col1;
    if (h < 32)       col1 = h * 128 + t;
    else if (h < 40)  col1 = 4096 + (h - 32) * 128 + t;
    else              col1 = 5120 + (h - 40) * 128 + t;
    const int col2 = col1 + 64;

    float x1 = 0.f, x2 = 0.f;
#pragma unroll
    for (int s = 0; s < SPLITS; s++) {
        x1 += g_qkv_part[(s * 32 + b) * QKVC + col1];
        x2 += g_qkv_part[(s * 32 + b) * QKVC + col2];
    }

    float o1 = x1, o2 = x2;
    if (h < 40) {
        float pos = (float)pos_ids[b];
        // inv_freq = theta^(-2t/128); compute in double, round to f32 (matches jax f32 pipeline to ~1ulp)
        float invf = (float)exp(-((double)(2 * t) / 128.0) * 13.815510557964274); // ln(1e6)
        float ang = pos * invf;
        float c = cosf(ang), sn = sinf(ang);
        o1 = x1 * c - x2 * sn;
        o2 = x2 * c + x1 * sn;
    }
    if (h < 32) {
        const float sc = 0.08838834764831845f; // 1/sqrt(128), folded into q
        g_q[(b * H_ + h) * HD_ + t]      = o1 * sc;
        g_q[(b * H_ + h) * HD_ + t + 64] = o2 * sc;
    } else if (h < 40) {
        g_knew[(b * KV_ + (h - 32)) * HD_ + t]      = o1;
        g_knew[(b * KV_ + (h - 32)) * HD_ + t + 64] = o2;
    } else {
        g_vnew[(b * KV_ + (h - 40)) * HD_ + t]      = o1;
        g_vnew[(b * KV_ + (h - 40)) * HD_ + t + 64] = o2;
    }
}

// ---------------- paged attention: warp = one 64-row cache block, 4 GQA groups per warp
__global__ __launch_bounds__(256) void attn_kernel(
    const float* __restrict__ kc, const float* __restrict__ vc,
    const int* __restrict__ block_offsets, const int* __restrict__ kv_seqlens)
{
    const int kvh = blockIdx.x;          // 0..7
    const int s = blockIdx.y;            // 0..7
    const int b = blockIdx.z;            // 0..31
    const int w = threadIdx.x >> 5;      // 0..7
    const int lane = threadIdx.x & 31;
    const int seg = s * 8 + w;           // 0..63
    const int r0 = seg * 64;

    const int kvlen = kv_seqlens[b];
    const int last = kvlen - 1;
    int nrows = kvlen - r0;
    if (nrows > 64) nrows = 64;

    float4 q[4];
#pragma unroll
    for (int g = 0; g < 4; g++)
        q[g] = *(const float4*)&g_q[((size_t)b * H_ + kvh * 4 + g) * HD_ + lane * 4];

    float m[4], l[4];
    float4 acc[4];
#pragma unroll
    for (int g = 0; g < 4; g++) {
        m[g] = -1e30f; l[g] = 0.f;
        acc[g] = make_float4(0.f, 0.f, 0.f, 0.f);
    }

    if (nrows > 0) {
        const int phys = block_offsets[b * NBLK_ + seg];
        const float* kb = kc + (size_t)phys * (BLOCK_ * KV_ * HD_) + kvh * HD_;
        const float* vb = vc + (size_t)phys * (BLOCK_ * KV_ * HD_) + kvh * HD_;

#pragma unroll 2
        for (int i = 0; i < nrows; i++) {
            const int gr = r0 + i;
            const float* kp = kb + i * (KV_ * HD_);
            const float* vp = vb + i * (KV_ * HD_);
            if (gr == last) {  // decode token: use freshly computed k/v instead of cache
                kp = &g_knew[(b * KV_ + kvh) * HD_];
                vp = &g_vnew[(b * KV_ + kvh) * HD_];
            }
            float4 k4 = *(const float4*)(kp + lane * 4);
            float4 v4 = *(const float4*)(vp + lane * 4);

            float sc[4];
#pragma unroll
            for (int g = 0; g < 4; g++) {
                sc[g] = fmaf(q[g].x, k4.x,
                         fmaf(q[g].y, k4.y,
                          fmaf(q[g].z, k4.z, q[g].w * k4.w)));
            }
#pragma unroll
            for (int off = 16; off > 0; off >>= 1) {
#pragma unroll
                for (int g = 0; g < 4; g++)
                    sc[g] += __shfl_xor_sync(0xffffffffu, sc[g], off);
            }
#pragma unroll
            for (int g = 0; g < 4; g++) {
                float sg = sc[g];
                if (sg <= m[g]) {
                    float p = __expf(sg - m[g]);
                    l[g] += p;
                    acc[g].x = fmaf(p, v4.x, acc[g].x);
                    acc[g].y = fmaf(p, v4.y, acc[g].y);
                    acc[g].z = fmaf(p, v4.z, acc[g].z);
                    acc[g].w = fmaf(p, v4.w, acc[g].w);
                } else {
                    float al = __expf(m[g] - sg);
                    m[g] = sg;
                    l[g] = fmaf(l[g], al, 1.0f);
                    acc[g].x = fmaf(acc[g].x, al, v4.x);
                    acc[g].y = fmaf(acc[g].y, al, v4.y);
                    acc[g].z = fmaf(acc[g].z, al, v4.z);
                    acc[g].w = fmaf(acc[g].w, al, v4.w);
                }
            }
        }
    }

#pragma unroll
    for (int g = 0; g < 4; g++) {
        const size_t hh = (size_t)b * H_ + kvh * 4 + g;
        *(float4*)&g_attn_acc[(hh * SEGS + seg) * HD_ + lane * 4] = acc[g];
        if (lane == 0) {
            g_attn_ml[(hh * SEGS + seg) * 2 + 0] = m[g];
            g_attn_ml[(hh * SEGS + seg) * 2 + 1] = l[g];
        }
    }
}

// ---------------- combine split-softmax partials -> attn output
__global__ __launch_bounds__(128) void combine_kernel()
{
    const int h = blockIdx.x;
    const int b = blockIdx.y;
    const int t = threadIdx.x;  // 0..127 (head dim)
    __shared__ float sm[SEGS], sl[SEGS], sw[SEGS];

    const size_t mlbase = ((size_t)b * H_ + h) * SEGS;
    if (t < SEGS) {
        sm[t] = g_attn_ml[(mlbase + t) * 2 + 0];
        sl[t] = g_attn_ml[(mlbase + t) * 2 + 1];
    }
    __syncthreads();
    float M = -1e30f;
#pragma unroll
    for (int q2 = 0; q2 < SEGS; q2++) M = fmaxf(M, sm[q2]);
    if (t < SEGS) sw[t] = __expf(sm[t] - M);
    __syncthreads();

    float denom = 0.f;
#pragma unroll 8
    for (int q2 = 0; q2 < SEGS; q2++) denom = fmaf(sw[q2], sl[q2], denom);

    float sum = 0.f;
    const float* accb = g_attn_acc + mlbase * HD_ + t;
#pragma unroll 8
    for (int q2 = 0; q2 < SEGS; q2++) sum = fmaf(sw[q2], accb[q2 * HD_], sum);

    g_attn_out[b * DM + h * HD_ + t] = sum / denom;
}

// ---------------- final split-K reduce for output projection
__global__ __launch_bounds__(256) void final_reduce_kernel(float* __restrict__ out)
{
    const int idx = blockIdx.x * 256 + threadIdx.x;  // < 32*4096
    float s = 0.f;
#pragma unroll
    for (int p = 0; p < SPLITS; p++) s += g_out_part[p * (B_ * DM) + idx];
    out[idx] = s;
}

// ---------------- launch ----------------
extern "C" void kernel_launch(void* const* d_in, const int* in_sizes, int n_in,
                              void* d_out, int out_size)
{
    const float* hidden = (const float*)d_in[0];
    const float* wqkv   = (const float*)d_in[1];
    const float* wo     = (const float*)d_in[2];
    const float* kc     = (const float*)d_in[3];
    const float* vc     = (const float*)d_in[4];
    const int* pos      = (const int*)d_in[5];
    const int* boff     = (const int*)d_in[6];
    const int* kvl      = (const int*)d_in[7];
    float* out          = (float*)d_out;

    // QKV projection (split-K partials)
    gemm_splitk_kernel<<<dim3(QKVC / 128, SPLITS), 256>>>(hidden, wqkv, QKVC, 0);
    // reduce + RoPE + stash new k/v
    rope_kernel<<<dim3(48, B_), 64>>>(pos);
    // paged attention with split softmax
    attn_kernel<<<dim3(KV_, 8, B_), 256>>>(kc, vc, boff, kvl);
    // combine partials
    combine_kernel<<<dim3(H_, B_), 128>>>();
    // output projection (split-K partials)
    gemm_splitk_kernel<<<dim3(DM / 128, SPLITS), 256>>>(nullptr, wo, DM, 1);
    // final reduce -> d_out
    final_reduce_kernel<<<dim3((B_ * DM) / 256), 256>>>(out);
}

// round 3
// speedup vs baseline: 1.3478x; 1.3478x over previous
#include <cuda_runtime.h>
#include <math.h>

// ---------------- problem constants ----------------
#define B_      32
#define DM      4096
#define H_      32
#define KV_     8
#define G_      4
#define HD_     128
#define BLOCK_  64
#define NBLK_   64
#define L_      4096
#define QKVC    6144   // (H + 2*KV) * HD
#define SPLITS  8      // split-K for GEMMs
#define SEGS    64     // attention segments per sequence (one 64-row block each)

// ---------------- scratch (__device__ globals; no allocation) ----------------
__device__ float g_qkv_part[SPLITS * B_ * QKVC];
__device__ float g_q[B_ * H_ * HD_];
__device__ float g_knew[B_ * KV_ * HD_];
__device__ float g_vnew[B_ * KV_ * HD_];
__device__ float g_attn_acc[(size_t)B_ * H_ * SEGS * HD_];
__device__ float g_attn_ml[B_ * H_ * SEGS * 2];
__device__ float g_attn_out[B_ * DM];
__device__ float g_out_part[SPLITS * B_ * DM];

// ---------------- split-K GEMM with packed f32x2 FMA ----------------
// out_part[s][b][col] = sum_{d in chunk} A[b][d]*W[d][col]
__global__ __launch_bounds__(256) void gemm_splitk_kernel(
    const float* __restrict__ A_in, const float* __restrict__ W, int ncols, int which)
{
    __shared__ __align__(16) float2 hs2[32][128];   // duplicated (h,h) pairs, 32KB
    const float* A = which ? g_attn_out : A_in;
    float* part = which ? g_out_part : g_qkv_part;

    const int tid = threadIdx.x;
    const int tc = tid & 31;            // 32 col-groups of 4 cols
    const int tr = tid >> 5;            // 8 batch-groups of 4 batches
    const int col4 = blockIdx.x * 128 + tc * 4;
    const int s = blockIdx.y;

    unsigned long long acc0[4] = {0ull, 0ull, 0ull, 0ull};  // cols (0,1) per batch j
    unsigned long long acc1[4] = {0ull, 0ull, 0ull, 0ull};  // cols (2,3) per batch j

    for (int sub = 0; sub < 4; sub++) {
        const int dd0 = s * 512 + sub * 128;
        for (int i = tid; i < 1024; i += 256) {
            int bb = i >> 5;
            int cc = i & 31;
            float4 v = *(const float4*)&A[bb * DM + dd0 + cc * 4];
            *(float4*)&hs2[bb][cc * 4]     = make_float4(v.x, v.x, v.y, v.y);
            *(float4*)&hs2[bb][cc * 4 + 2] = make_float4(v.z, v.z, v.w, v.w);
        }
        __syncthreads();
#pragma unroll 4
        for (int dd = 0; dd < 128; dd++) {
            float4 wv = *(const float4*)&W[(size_t)(dd0 + dd) * ncols + col4];
            unsigned long long p0, p1;
            asm("mov.b64 %0, {%1,%2};" : "=l"(p0) : "f"(wv.x), "f"(wv.y));
            asm("mov.b64 %0, {%1,%2};" : "=l"(p1) : "f"(wv.z), "f"(wv.w));
#pragma unroll
            for (int j = 0; j < 4; j++) {
                unsigned long long hb = *(const unsigned long long*)&hs2[tr * 4 + j][dd];
                asm("fma.rn.f32x2 %0, %1, %2, %0;" : "+l"(acc0[j]) : "l"(hb), "l"(p0));
                asm("fma.rn.f32x2 %0, %1, %2, %0;" : "+l"(acc1[j]) : "l"(hb), "l"(p1));
            }
        }
        __syncthreads();
    }
#pragma unroll
    for (int j = 0; j < 4; j++) {
        float o0, o1, o2, o3;
        asm("mov.b64 {%0,%1}, %2;" : "=f"(o0), "=f"(o1) : "l"(acc0[j]));
        asm("mov.b64 {%0,%1}, %2;" : "=f"(o2), "=f"(o3) : "l"(acc1[j]));
        int bb = tr * 4 + j;
        *(float4*)&part[((size_t)s * 32 + bb) * ncols + col4] = make_float4(o0, o1, o2, o3);
    }
}

// ---------------- reduce qkv partials + RoPE + stash new k/v ----------------
__global__ __launch_bounds__(64) void rope_kernel(const int* __restrict__ pos_ids)
{
    const int h = blockIdx.x;   // 0..47: 0-31 q heads, 32-39 k heads, 40-47 v heads
    const int b = blockIdx.y;
    const int t = threadIdx.x;  // 0..63 (pair t, t+64)

    int col1;
    if (h < 32)       col1 = h * 128 + t;
    else if (h < 40)  col1 = 4096 + (h - 32) * 128 + t;
    else              col1 = 5120 + (h - 40) * 128 + t;
    const int col2 = col1 + 64;

    float x1 = 0.f, x2 = 0.f;
#pragma unroll
    for (int s = 0; s < SPLITS; s++) {
        x1 += g_qkv_part[(s * 32 + b) * QKVC + col1];
        x2 += g_qkv_part[(s * 32 + b) * QKVC + col2];
    }

    float o1 = x1, o2 = x2;
    if (h < 40) {
        float pos = (float)pos_ids[b];
        float invf = (float)exp(-((double)(2 * t) / 128.0) * 13.815510557964274); // ln(1e6)
        float ang = pos * invf;
        float c = cosf(ang), sn = sinf(ang);
        o1 = x1 * c - x2 * sn;
        o2 = x2 * c + x1 * sn;
    }
    if (h < 32) {
        const float sc = 0.08838834764831845f; // 1/sqrt(128) folded into q
        g_q[(b * H_ + h) * HD_ + t]      = o1 * sc;
        g_q[(b * H_ + h) * HD_ + t + 64] = o2 * sc;
    } else if (h < 40) {
        g_knew[(b * KV_ + (h - 32)) * HD_ + t]      = o1;
        g_knew[(b * KV_ + (h - 32)) * HD_ + t + 64] = o2;
    } else {
        g_vnew[(b * KV_ + (h - 40)) * HD_ + t]      = o1;
        g_vnew[(b * KV_ + (h - 40)) * HD_ + t + 64] = o2;
    }
}

// ---------------- paged attention: half-warp per row, 2 rows/warp-step ----------------
// lane = half*16 + sub; sub covers dims [sub*8, sub*8+8); half covers row parity.
__global__ __launch_bounds__(128) void attn_kernel(
    const float* __restrict__ kc, const float* __restrict__ vc,
    const int* __restrict__ block_offsets, const int* __restrict__ kv_seqlens)
{
    const int kvh = blockIdx.x;          // 0..7
    const int sblk = blockIdx.y;         // 0..15
    const int b = blockIdx.z;            // 0..31
    const int w = threadIdx.x >> 5;      // 0..3
    const int lane = threadIdx.x & 31;
    const int half = lane >> 4;
    const int sub = lane & 15;
    const int seg = sblk * 4 + w;        // 0..63
    const int r0 = seg * 64;

    const int kvlen = kv_seqlens[b];
    const int last = kvlen - 1;

    float4 qa[4], qb[4];
    const float* qbase = g_q + ((size_t)b * H_ + kvh * 4) * HD_ + sub * 8;
#pragma unroll
    for (int g = 0; g < 4; g++) {
        qa[g] = *(const float4*)(qbase + g * HD_);
        qb[g] = *(const float4*)(qbase + g * HD_ + 4);
    }

    float m[4], l[4];
    float4 aa[4], ab[4];
#pragma unroll
    for (int g = 0; g < 4; g++) {
        m[g] = -3e38f; l[g] = 0.f;
        aa[g] = make_float4(0.f, 0.f, 0.f, 0.f);
        ab[g] = make_float4(0.f, 0.f, 0.f, 0.f);
    }

    if (r0 < kvlen) {
        const int phys = block_offsets[b * NBLK_ + seg];
        const float* kb_ = kc + (size_t)phys * (BLOCK_ * KV_ * HD_) + kvh * HD_ + sub * 8;
        const float* vb_ = vc + (size_t)phys * (BLOCK_ * KV_ * HD_) + kvh * HD_ + sub * 8;
        const float* knew = g_knew + ((size_t)b * KV_ + kvh) * HD_ + sub * 8;
        const float* vnew = g_vnew + ((size_t)b * KV_ + kvh) * HD_ + sub * 8;

        // prefetch first row pair (row = half)
        const float* kp = (r0 + half == last) ? knew : kb_ + (size_t)half * (KV_ * HD_);
        const float* vp = (r0 + half == last) ? vnew : vb_ + (size_t)half * (KV_ * HD_);
        float4 ka = __ldcs((const float4*)kp);
        float4 kb2 = __ldcs((const float4*)(kp + 4));
        float4 va = __ldcs((const float4*)vp);
        float4 vb2 = __ldcs((const float4*)(vp + 4));

        for (int ip = 0; ip < 32; ip++) {
            float4 nka, nkb, nva, nvb;
            if (ip < 31) {
                int ni = 2 * (ip + 1) + half;
                const float* nk = (r0 + ni == last) ? knew : kb_ + (size_t)ni * (KV_ * HD_);
                const float* nv = (r0 + ni == last) ? vnew : vb_ + (size_t)ni * (KV_ * HD_);
                nka = __ldcs((const float4*)nk);
                nkb = __ldcs((const float4*)(nk + 4));
                nva = __ldcs((const float4*)nv);
                nvb = __ldcs((const float4*)(nv + 4));
            }

            const int r = r0 + 2 * ip + half;
            float sc[4];
#pragma unroll
            for (int g = 0; g < 4; g++) {
                float t0 = qa[g].x * ka.x;
                t0 = fmaf(qa[g].y, ka.y, t0);
                t0 = fmaf(qa[g].z, ka.z, t0);
                t0 = fmaf(qa[g].w, ka.w, t0);
                t0 = fmaf(qb[g].x, kb2.x, t0);
                t0 = fmaf(qb[g].y, kb2.y, t0);
                t0 = fmaf(qb[g].z, kb2.z, t0);
                t0 = fmaf(qb[g].w, kb2.w, t0);
                sc[g] = t0;
            }
            // butterfly within 16-lane halves (offsets 8,4,2,1)
#pragma unroll
            for (int off = 8; off > 0; off >>= 1) {
#pragma unroll
                for (int g = 0; g < 4; g++)
                    sc[g] += __shfl_xor_sync(0xffffffffu, sc[g], off);
            }

#pragma unroll
            for (int g = 0; g < 4; g++) {
                float sg = (r < kvlen) ? sc[g] : -1e30f;
                if (sg <= m[g]) {
                    float p = __expf(sg - m[g]);
                    l[g] += p;
                    aa[g].x = fmaf(p, va.x, aa[g].x);
                    aa[g].y = fmaf(p, va.y, aa[g].y);
                    aa[g].z = fmaf(p, va.z, aa[g].z);
                    aa[g].w = fmaf(p, va.w, aa[g].w);
                    ab[g].x = fmaf(p, vb2.x, ab[g].x);
                    ab[g].y = fmaf(p, vb2.y, ab[g].y);
                    ab[g].z = fmaf(p, vb2.z, ab[g].z);
                    ab[g].w = fmaf(p, vb2.w, ab[g].w);
                } else {
                    float al = __expf(m[g] - sg);
                    m[g] = sg;
                    l[g] = fmaf(l[g], al, 1.0f);
                    aa[g].x = fmaf(aa[g].x, al, va.x);
                    aa[g].y = fmaf(aa[g].y, al, va.y);
                    aa[g].z = fmaf(aa[g].z, al, va.z);
                    aa[g].w = fmaf(aa[g].w, al, va.w);
                    ab[g].x = fmaf(ab[g].x, al, vb2.x);
                    ab[g].y = fmaf(ab[g].y, al, vb2.y);
                    ab[g].z = fmaf(ab[g].z, al, vb2.z);
                    ab[g].w = fmaf(ab[g].w, al, vb2.w);
                }
            }
            ka = nka; kb2 = nkb; va = nva; vb2 = nvb;
        }
    }

    // merge the two half-warp softmax states (each lane ends with full-row state for its dims)
#pragma unroll
    for (int g = 0; g < 4; g++) {
        float om = __shfl_xor_sync(0xffffffffu, m[g], 16);
        float ol = __shfl_xor_sync(0xffffffffu, l[g], 16);
        float4 oaa, oab;
        oaa.x = __shfl_xor_sync(0xffffffffu, aa[g].x, 16);
        oaa.y = __shfl_xor_sync(0xffffffffu, aa[g].y, 16);
        oaa.z = __shfl_xor_sync(0xffffffffu, aa[g].z, 16);
        oaa.w = __shfl_xor_sync(0xffffffffu, aa[g].w, 16);
        oab.x = __shfl_xor_sync(0xffffffffu, ab[g].x, 16);
        oab.y = __shfl_xor_sync(0xffffffffu, ab[g].y, 16);
        oab.z = __shfl_xor_sync(0xffffffffu, ab[g].z, 16);
        oab.w = __shfl_xor_sync(0xffffffffu, ab[g].w, 16);
        float nm = fmaxf(m[g], om);
        float wa = __expf(m[g] - nm);
        float wb = __expf(om - nm);
        l[g] = l[g] * wa + ol * wb;
        aa[g].x = aa[g].x * wa + oaa.x * wb;
        aa[g].y = aa[g].y * wa + oaa.y * wb;
        aa[g].z = aa[g].z * wa + oaa.z * wb;
        aa[g].w = aa[g].w * wa + oaa.w * wb;
        ab[g].x = ab[g].x * wa + oab.x * wb;
        ab[g].y = ab[g].y * wa + oab.y * wb;
        ab[g].z = ab[g].z * wa + oab.z * wb;
        ab[g].w = ab[g].w * wa + oab.w * wb;
        m[g] = nm;
    }

#pragma unroll
    for (int g = 0; g < 4; g++) {
        const size_t base = (((size_t)b * H_ + kvh * 4 + g) * SEGS + seg) * HD_;
        if (half == 0)
            *(float4*)&g_attn_acc[base + sub * 8] = aa[g];
        else
            *(float4*)&g_attn_acc[base + sub * 8 + 4] = ab[g];
    }
    if (lane == 0) {
#pragma unroll
        for (int g = 0; g < 4; g++) {
            const size_t mb = ((size_t)b * H_ + kvh * 4 + g) * SEGS + seg;
            g_attn_ml[mb * 2 + 0] = m[g];
            g_attn_ml[mb * 2 + 1] = l[g];
        }
    }
}

// ---------------- combine split-softmax partials -> attn output ----------------
// warp per head; lane owns 4 dims (float4)
__global__ __launch_bounds__(128) void combine_kernel()
{
    const int w = threadIdx.x >> 5;
    const int lane = threadIdx.x & 31;
    const int h = blockIdx.x * 4 + w;
    const int b = blockIdx.y;
    const size_t hh = (size_t)b * H_ + h;

    __shared__ float sw[4][SEGS];

    // lane covers segs 2*lane, 2*lane+1
    float4 ml2 = *(const float4*)&g_attn_ml[(hh * SEGS + lane * 2) * 2]; // m0,l0,m1,l1
    float mx = fmaxf(ml2.x, ml2.z);
#pragma unroll
    for (int off = 16; off > 0; off >>= 1)
        mx = fmaxf(mx, __shfl_xor_sync(0xffffffffu, mx, off));
    float w0 = __expf(ml2.x - mx), w1 = __expf(ml2.z - mx);
    float denom = fmaf(w0, ml2.y, w1 * ml2.w);
#pragma unroll
    for (int off = 16; off > 0; off >>= 1)
        denom += __shfl_xor_sync(0xffffffffu, denom, off);
    sw[w][lane * 2] = w0;
    sw[w][lane * 2 + 1] = w1;
    __syncwarp();

    float4 sum = make_float4(0.f, 0.f, 0.f, 0.f);
    const float* accb = g_attn_acc + hh * SEGS * HD_ + lane * 4;
#pragma unroll 8
    for (int s = 0; s < SEGS; s++) {
        float ws = sw[w][s];
        float4 a = *(const float4*)(accb + (size_t)s * HD_);
        sum.x = fmaf(ws, a.x, sum.x);
        sum.y = fmaf(ws, a.y, sum.y);
        sum.z = fmaf(ws, a.z, sum.z);
        sum.w = fmaf(ws, a.w, sum.w);
    }
    float inv = 1.0f / denom;
    *(float4*)&g_attn_out[(size_t)b * DM + h * HD_ + lane * 4] =
        make_float4(sum.x * inv, sum.y * inv, sum.z * inv, sum.w * inv);
}

// ---------------- final split-K reduce for output projection ----------------
__global__ __launch_bounds__(256) void final_reduce_kernel(float* __restrict__ out)
{
    const int idx = blockIdx.x * 256 + threadIdx.x;
    float s = 0.f;
#pragma unroll
    for (int p = 0; p < SPLITS; p++) s += g_out_part[p * (B_ * DM) + idx];
    out[idx] = s;
}

// ---------------- launch ----------------
extern "C" void kernel_launch(void* const* d_in, const int* in_sizes, int n_in,
                              void* d_out, int out_size)
{
    const float* hidden = (const float*)d_in[0];
    const float* wqkv   = (const float*)d_in[1];
    const float* wo     = (const float*)d_in[2];
    const float* kc     = (const float*)d_in[3];
    const float* vc     = (const float*)d_in[4];
    const int* pos      = (const int*)d_in[5];
    const int* boff     = (const int*)d_in[6];
    const int* kvl      = (const int*)d_in[7];
    float* out          = (float*)d_out;

    gemm_splitk_kernel<<<dim3(QKVC / 128, SPLITS), 256>>>(hidden, wqkv, QKVC, 0);
    rope_kernel<<<dim3(48, B_), 64>>>(pos);
    attn_kernel<<<dim3(KV_, 16, B_), 128>>>(kc, vc, boff, kvl);
    combine_kernel<<<dim3(H_ / 4, B_), 128>>>();
    gemm_splitk_kernel<<<dim3(DM / 128, SPLITS), 256>>>(nullptr, wo, DM, 1);
    final_reduce_kernel<<<dim3((B_ * DM) / 256), 256>>>(out);
}